// round 17
// baseline (speedup 1.0000x reference)
#include <cuda_runtime.h>
#include <cuda_fp16.h>
#include <cstdint>

// Implicit-GEMM 3x3 conv, single-pass fp16 mma.sync, fp32 accum.
// R14: 3-stage cp.async B pipeline (wait_group 1) + ldmatrix fragment
// double-buffering across k16 steps to overlap crossbar with tensor pipe.

#define CONV_HW  56
#define CONV_PIX 3136
#define CONV_K   256
#define GEMM_K   2304
#define X_ELEMS  (32 * 256 * CONV_PIX)
#define W_ELEMS  (CONV_K * GEMM_K)
#define BK       64
#define NCHUNK   (GEMM_K / BK)             // 36

#define PITCH_B  144                       // 64 fp16 payload (128B) + 16B pad
#define A_BYTES  (128 * PITCH_B)           // 18432
#define B_BYTES  (256 * PITCH_B)           // 36864
// layout: A0, A1, B0, B1, B2
#define OFF_B    (2 * A_BYTES)             // 36864
#define SMEM_TOTAL (2 * A_BYTES + 3 * B_BYTES)   // 147456

__device__ unsigned short g_xh[X_ELEMS];   // fp16 bits of x
__device__ unsigned short g_wh[W_ELEMS];   // fp16 bits of w

__device__ __forceinline__ uint32_t smem_u32(const void* p) {
    uint32_t a;
    asm("{ .reg .u64 t; cvta.to.shared.u64 t, %1; cvt.u32.u64 %0, t; }" : "=r"(a) : "l"(p));
    return a;
}
__device__ __forceinline__ void cp_async16(uint32_t dst, const void* src) {
    asm volatile("cp.async.cg.shared.global [%0], [%1], 16;" :: "r"(dst), "l"(src));
}
#define CP_COMMIT() asm volatile("cp.async.commit_group;" ::: "memory")
#define CP_WAIT1()  asm volatile("cp.async.wait_group 1;" ::: "memory")
#define CP_WAIT0()  asm volatile("cp.async.wait_group 0;" ::: "memory")

#define LDSM_X4(r0, r1, r2, r3, a) \
    asm volatile("ldmatrix.sync.aligned.m8n8.x4.shared.b16 {%0,%1,%2,%3}, [%4];" \
                 : "=r"(r0), "=r"(r1), "=r"(r2), "=r"(r3) : "r"(a))

#define MMAF16(c, a, b) \
    asm volatile("mma.sync.aligned.m16n8k16.row.col.f32.f16.f16.f32 " \
                 "{%0,%1,%2,%3}, {%4,%5,%6,%7}, {%8,%9}, {%0,%1,%2,%3};" \
                 : "+f"((c)[0]), "+f"((c)[1]), "+f"((c)[2]), "+f"((c)[3]) \
                 : "r"((a)[0]), "r"((a)[1]), "r"((a)[2]), "r"((a)[3]), \
                   "r"((b)[0]), "r"((b)[1]))

// ---------------- prep kernels ----------------

__global__ void cvt_x_kernel(const float* __restrict__ x) {
    const int i8 = blockIdx.x * blockDim.x + threadIdx.x;
    if (i8 * 8 >= X_ELEMS) return;
    const float4 v0 = *(const float4*)(x + (size_t)i8 * 8);
    const float4 v1 = *(const float4*)(x + (size_t)i8 * 8 + 4);
    __half2 h0 = __floats2half2_rn(v0.x, v0.y);
    __half2 h1 = __floats2half2_rn(v0.z, v0.w);
    __half2 h2 = __floats2half2_rn(v1.x, v1.y);
    __half2 h3 = __floats2half2_rn(v1.z, v1.w);
    uint4 o;
    o.x = *reinterpret_cast<uint32_t*>(&h0);
    o.y = *reinterpret_cast<uint32_t*>(&h1);
    o.z = *reinterpret_cast<uint32_t*>(&h2);
    o.w = *reinterpret_cast<uint32_t*>(&h3);
    *(uint4*)(g_xh + (size_t)i8 * 8) = o;
}

__global__ void cvt_w_kernel(const float* __restrict__ w) {
    const int i = blockIdx.x * blockDim.x + threadIdx.x;
    if (i * 2 >= W_ELEMS) return;
    const float2 v = *(const float2*)(w + (size_t)i * 2);
    __half2 h = __floats2half2_rn(v.x, v.y);
    *(uint32_t*)(g_wh + (size_t)i * 2) = *reinterpret_cast<uint32_t*>(&h);
}

// ---------------- main kernel ----------------

__global__ __launch_bounds__(512, 1)
void conv3x3_f16_kernel(float* __restrict__ out) {
    extern __shared__ char smem[];
    const uint32_t sbase = smem_u32(smem);
    const int tid  = threadIdx.x;
    const int wrp  = tid >> 5;
    const int lane = tid & 31;

    const int block_m = blockIdx.x * 128;

    // ---- A staging: m = tid&127, kg = (tid>>7)*16
    const int a_m  = tid & 127;
    const int a_kg = (tid >> 7) * 16;
    const int p_a    = block_m + a_m;
    const int nimg_a = p_a / CONV_PIX;
    const int hw_a   = p_a - nimg_a * CONV_PIX;
    const int oh     = hw_a / CONV_HW;
    const int ow     = hw_a - oh * CONV_HW;
    const unsigned short* xs_n = g_xh + (size_t)nimg_a * CONV_K * CONV_PIX;

    // ---- B staging via cp.async: row = tid>>1 (0..255), 4x16B per thread
    const int b_row = tid >> 1;
    const int b_q0  = (tid & 1) * 4;
    const unsigned short* whp = g_wh + (size_t)b_row * GEMM_K + b_q0 * 8;
    const uint32_t b_sts = (uint32_t)b_row * PITCH_B + (uint32_t)b_q0 * 16;

    // ---- warp tile 32x64
    const int m0 = (wrp & 3) * 32;
    const int n0 = (wrp >> 2) * 64;

    const uint32_t a_lm_off = (uint32_t)(m0 + (lane & 15)) * PITCH_B + (uint32_t)(lane >> 4) * 16;
    const uint32_t b_lm_off = (uint32_t)(n0 + (lane & 7) + ((lane >> 4) << 3)) * PITCH_B
                            + (uint32_t)((lane >> 3) & 1) * 16;

    float acc[2][8][4];
    #pragma unroll
    for (int i = 0; i < 2; i++)
        #pragma unroll
        for (int j = 0; j < 8; j++)
            #pragma unroll
            for (int r = 0; r < 4; r++) acc[i][j][r] = 0.f;

    unsigned short axv[16];

    auto load_A = [&](int kt) {
        int k0 = kt + a_kg;
        int c  = k0 / 9;
        int rs = k0 - c * 9;
        int r  = rs / 3;
        int s  = rs - r * 3;
        const unsigned short* xc = xs_n + c * CONV_PIX;
        #pragma unroll
        for (int j = 0; j < 16; j++) {
            const int ih = oh + r - 1, iw = ow + s - 1;
            const bool ok = ((unsigned)ih < CONV_HW) && ((unsigned)iw < CONV_HW);
            axv[j] = ok ? __ldg(xc + ih * CONV_HW + iw) : (unsigned short)0;
            if (++s == 3) { s = 0; if (++r == 3) { r = 0; xc += CONV_PIX; } }
        }
    };
    auto store_A = [&](char* st) {
        uint32_t p[8];
        #pragma unroll
        for (int t = 0; t < 8; t++)
            p[t] = (uint32_t)axv[2*t] | ((uint32_t)axv[2*t+1] << 16);
        const uint32_t off = (uint32_t)a_m * PITCH_B + (uint32_t)a_kg * 2;
        *(uint4*)(st + off)      = make_uint4(p[0], p[1], p[2], p[3]);
        *(uint4*)(st + off + 16) = make_uint4(p[4], p[5], p[6], p[7]);
    };
    auto issue_B = [&](uint32_t bbuf_base, int kt) {
        #pragma unroll
        for (int q = 0; q < 4; q++)
            cp_async16(bbuf_base + b_sts + q * 16, whp + kt + q * 8);
        CP_COMMIT();
    };

    auto ldA2 = [&](uint32_t abuf, uint32_t kso, uint32_t (&a)[2][4]) {
        #pragma unroll
        for (int mt = 0; mt < 2; mt++)
            LDSM_X4(a[mt][0], a[mt][1], a[mt][2], a[mt][3],
                    abuf + a_lm_off + kso + (uint32_t)mt * 16 * PITCH_B);
    };
    auto ldB4 = [&](uint32_t bbuf, uint32_t kso, uint32_t (&b)[4][4]) {
        #pragma unroll
        for (int t = 0; t < 4; t++)
            LDSM_X4(b[t][0], b[t][1], b[t][2], b[t][3],
                    bbuf + b_lm_off + kso + (uint32_t)t * 16 * PITCH_B);
    };
    auto mma_pass = [&](uint32_t (&a)[2][4], uint32_t (&b)[4][4]) {
        #pragma unroll
        for (int mt = 0; mt < 2; mt++)
            #pragma unroll
            for (int nt = 0; nt < 8; nt++)
                MMAF16(acc[mt][nt], a[mt], &b[nt >> 1][(nt & 1) * 2]);
    };

    // prologue: B chunks 0,1 in flight; A chunk 0 staged
    issue_B(sbase + OFF_B, 0);
    issue_B(sbase + OFF_B + B_BYTES, BK);
    load_A(0);
    store_A(smem);
    CP_WAIT1();            // B0 complete (B1 may be in flight)
    __syncthreads();

    int bbuf_idx = 0;      // B buffer for current chunk
    for (int c = 0; c < NCHUNK; ++c) {
        const int abuf_idx = c & 1;
        const uint32_t abuf = sbase + (uint32_t)abuf_idx * A_BYTES;
        const uint32_t bbuf = sbase + OFF_B + (uint32_t)bbuf_idx * B_BYTES;
        const bool more = (c + 1) < NCHUNK;

        if (c + 2 < NCHUNK) {
            const int nb2 = (bbuf_idx + 2) % 3;
            issue_B(sbase + OFF_B + (uint32_t)nb2 * B_BYTES, (c + 2) * BK);
        }
        if (more) load_A((c + 1) * BK);

        // ---- frag-double-buffered k16 steps ----
        uint32_t a[2][2][4], b[2][4][4];
        ldB4(bbuf, 0, b[0]);
        ldA2(abuf, 0, a[0]);
        #pragma unroll
        for (int ks = 0; ks < 4; ks++) {
            const int cur = ks & 1;
            if (ks < 3) {
                ldB4(bbuf, (uint32_t)(ks + 1) * 32, b[cur ^ 1]);
                ldA2(abuf, (uint32_t)(ks + 1) * 32, a[cur ^ 1]);
            }
            if (ks == 0 && more) store_A(smem + (abuf_idx ^ 1) * A_BYTES);
            mma_pass(a[cur], b[cur]);
        }

        CP_WAIT1();        // next chunk's B complete; at most 1 group in flight
        __syncthreads();
        bbuf_idx = (bbuf_idx + 1) % 3;
    }

    // ---- epilogue
    const int oc_base = n0 + (lane & 3) * 2;
    #pragma unroll
    for (int mt = 0; mt < 2; mt++) {
        const int p_lo = block_m + m0 + mt * 16 + (lane >> 2);
        const int p_hi = p_lo + 8;
        const int nl = p_lo / CONV_PIX, hl = p_lo - nl * CONV_PIX;
        const int nh = p_hi / CONV_PIX, hh = p_hi - nh * CONV_PIX;
        float* olo = out + (size_t)nl * CONV_K * CONV_PIX + hl;
        float* ohi = out + (size_t)nh * CONV_K * CONV_PIX + hh;
        #pragma unroll
        for (int nt = 0; nt < 8; nt++) {
            const int oc = oc_base + nt * 8;
            olo[(size_t)(oc    ) * CONV_PIX] = acc[mt][nt][0];
            olo[(size_t)(oc + 1) * CONV_PIX] = acc[mt][nt][1];
            ohi[(size_t)(oc    ) * CONV_PIX] = acc[mt][nt][2];
            ohi[(size_t)(oc + 1) * CONV_PIX] = acc[mt][nt][3];
        }
    }
}

extern "C" void kernel_launch(void* const* d_in, const int* in_sizes, int n_in,
                              void* d_out, int out_size) {
    const float* x = (const float*)d_in[0];
    const float* w = (const float*)d_in[1];
    float* out = (float*)d_out;

    cvt_x_kernel<<<(X_ELEMS / 8 + 255) / 256, 256>>>(x);
    cvt_w_kernel<<<(W_ELEMS / 2 + 255) / 256, 256>>>(w);

    cudaFuncSetAttribute(conv3x3_f16_kernel,
                         cudaFuncAttributeMaxDynamicSharedMemorySize, SMEM_TOTAL);
    dim3 grid(784, 1);
    conv3x3_f16_kernel<<<grid, 512, SMEM_TOTAL>>>(out);
}